// round 5
// baseline (speedup 1.0000x reference)
#include <cuda_runtime.h>
#include <math.h>

#define NB   2048
#define NDIM 128
#define MLZ  10
#define KAPPA 0.276f
#define TRI  8256      // 128*129/2
#define LPAD 8448      // packed tri, rows padded to multiple of 4 floats (= 2112 float4)

// dynamic smem: Lp[8448] | Tp[8448] | vcur[128] | vprev[128] | yv[128] | tv[128] | U1s[128]
#define SMEM_FLOATS (2 * LPAD + 5 * NDIM)
#define SMEM_BYTES  (SMEM_FLOATS * 4)

__device__ float    g_scr[2 * NB];   // [0..NB) max^2, [NB..2NB) min^2
__device__ unsigned g_ctr = 0;

__device__ __forceinline__ float blockReduceSum256(float v, float* red, int tid) {
    #pragma unroll
    for (int o = 16; o > 0; o >>= 1)
        v += __shfl_xor_sync(0xffffffffu, v, o);
    __syncthreads();                       // protect red[] from previous use
    if ((tid & 31) == 0) red[tid >> 5] = v;
    __syncthreads();
    return ((red[0] + red[1]) + (red[2] + red[3]))
         + ((red[4] + red[5]) + (red[6] + red[7]));
}

__device__ __forceinline__ int sturm_count(const float* a, const float* b2, float x) {
    float q = a[0] - x;
    int c = (q < 0.0f);
    #pragma unroll
    for (int i = 1; i < MLZ; i++) {
        float d = q;
        if (fabsf(d) < 1e-25f) d = (d < 0.0f) ? -1e-25f : 1e-25f;
        q = (a[i] - x) - b2[i - 1] / d;
        c += (q < 0.0f);
    }
    return c;
}

__global__ __launch_bounds__(256)
void spectrum_kernel(const float* __restrict__ net_out,
                     const float* __restrict__ U1,
                     const float* __restrict__ vin,
                     float* __restrict__ out) {
    extern __shared__ float sm[];
    float* Lp    = sm;                 // row i at f4 idx (g+1)*(2g+rm), g=i>>2, rm=i&3, padded len 4(g+1)
    float* Tp    = sm + LPAD;          // "row" j (= col j of L) at f4 idx 128g-2g(g-1)+rj(32-g), padded len 4(32-g)
    float* vcur  = sm + 2 * LPAD;      //   (element i stored at float offset i-4g within the row; front rj pads zero)
    float* vprev = vcur + NDIM;
    float* yv    = vprev + NDIM;
    float* tv    = yv + NDIM;
    float* U1s   = tv + NDIM;

    __shared__ float red[8];
    __shared__ float alph[MLZ], bet[MLZ], sc[4];
    __shared__ int   amLast;

    const int tid = threadIdx.x;
    const int b   = blockIdx.x;

    // ---- zero only the pad floats (384 total across both copies) ----
    if (tid < NDIM) {
        const int i = tid, g = i >> 2, rm = i & 3;
        float* rowL = Lp + (((g + 1) * (2 * g + rm)) << 2);
        #pragma unroll
        for (int p = 0; p < 3; p++)
            if (i + 1 + p < 4 * (g + 1)) rowL[i + 1 + p] = 0.0f;   // back pads: 3-rm
        float* rowT = Tp + (512 * g - 8 * g * (g - 1) + rm * (128 - 4 * g));
        #pragma unroll
        for (int p = 0; p < 3; p++)
            if (p < rm) rowT[p] = 0.0f;                            // front pads: rm
        U1s[tid] = U1[(size_t)b * NDIM + tid];
    }
    float v0 = (tid < NDIM) ? vin[(size_t)b * NDIM + tid] : 0.0f;

    // ---- build both padded packed copies (coalesced float4 reads) ----
    {
        const float4* src4 = (const float4*)(net_out + (size_t)b * TRI);
        for (int idx = tid; idx < TRI / 4; idx += 256) {
            float4 v4 = src4[idx];
            int k = idx << 2;
            int i = (int)((__fsqrt_rn(8.0f * (float)k + 1.0f) - 1.0f) * 0.5f);
            while ((i + 1) * (i + 2) / 2 <= k) ++i;
            while (i * (i + 1) / 2 > k) --i;
            int j = k - i * (i + 1) / 2;
            float vals[4] = {v4.x, v4.y, v4.z, v4.w};
            #pragma unroll
            for (int m = 0; m < 4; m++) {
                int gi = i >> 2, ri = i & 3;
                int gj = j >> 2, rj = j & 3;
                Lp[(((gi + 1) * (2 * gi + ri)) << 2) + j] = vals[m];
                Tp[512 * gj - 8 * gj * (gj - 1) + rj * (128 - 4 * gj) + i - 4 * gj] = vals[m];
                if (++j > i) { ++i; j = 0; }
            }
        }
    }

    // vn = v / ||v||  (the reduce's barriers also publish Lp/Tp/U1s)
    float nrm = sqrtf(blockReduceSum256(v0 * v0, red, tid));
    if (tid < NDIM) { vcur[tid] = v0 / nrm; vprev[tid] = 0.0f; }

    // ---- dd_opt stencil constants (element = tid for tid<128) ----
    const int te = tid & 127;
    const int ii = te >> 4, jj = (te >> 1) & 7, cc = te & 1;
    const int xip = (((ii + 1) & 7) << 4) | (jj << 1) | cc;
    const int xim = (((ii - 1) & 7) << 4) | (jj << 1) | cc;
    const int xjp = (ii << 4) | (((jj + 1) & 7) << 1) | cc;
    const int xjm = (ii << 4) | (((jj - 1) & 7) << 1) | cc;
    const float c_u0  = U1s[((ii << 3) + jj) << 1];     // U1s valid after reduce barrier
    const float c_u1  = U1s[(((ii << 3) + jj) << 1) + 1];
    const float c_u0m = U1s[((((ii - 1) & 7) << 3) + jj) << 1];
    const float c_u1m = U1s[(((ii << 3) + ((jj - 1) & 7)) << 1) + 1];

    // matvec bases: thread pair (ir = tid>>1, h = tid&1) per row
    const int ir  = tid >> 1;
    const int h   = tid & 1;
    const int gr  = ir >> 2;
    const int rb4 = (gr + 1) * (2 * gr + (ir & 3));                  // Lp row ir, f4
    const int tb4 = 128 * gr - 2 * gr * (gr - 1) + (ir & 3) * (32 - gr); // Tp row ir, f4
    const int tEnd = 31 - gr;                                        // t-phase last q
    const float4* Lp4 = (const float4*)Lp;
    const float4* Tp4 = (const float4*)Tp;
    const float4* yv4 = (const float4*)yv;
    const float4* tv4 = (const float4*)tv;

    float beta = 0.0f;
    __syncthreads();   // vcur visible

    for (int step = 0; step < MLZ; step++) {
        // ---- y = D x (hop stencil), element = tid < 128 ----
        if (tid < NDIM) {
            float xc  = vcur[tid];
            float hop = c_u0  * vcur[xip] + c_u1  * vcur[xjp]
                      + c_u0m * vcur[xim] + c_u1m * vcur[xjm];
            yv[tid] = xc - KAPPA * hop;
        }
        __syncthreads();

        // ---- t_j = (col j of L) . y  = Tp row ir dot yv : float4, h-split ----
        {
            float ax = 0.f, ay = 0.f, az = 0.f, aw = 0.f;
            #pragma unroll 2
            for (int q = h; q <= tEnd; q += 2) {
                float4 l  = Tp4[tb4 + q];
                float4 y4 = yv4[gr + q];
                ax += l.x * y4.x; ay += l.y * y4.y;
                az += l.z * y4.z; aw += l.w * y4.w;
            }
            float t = (ax + ay) + (az + aw);
            t += __shfl_xor_sync(0xffffffffu, t, 1);
            if (h == 0) tv[ir] = t;
        }
        __syncthreads();

        // ---- w_i = Lp row ir dot t : float4, h-split; stays in registers ----
        float wreg;
        {
            float ax = 0.f, ay = 0.f, az = 0.f, aw = 0.f;
            #pragma unroll 2
            for (int q = h; q <= gr; q += 2) {
                float4 l  = Lp4[rb4 + q];
                float4 t4 = tv4[q];
                ax += l.x * t4.x; ay += l.y * t4.y;
                az += l.z * t4.z; aw += l.w * t4.w;
            }
            wreg = (ax + ay) + (az + aw);
            wreg += __shfl_xor_sync(0xffffffffu, wreg, 1);   // both lanes hold full w_ir
        }

        // ---- Lanczos recurrence: h==0 lanes carry element ir ----
        float vc = vcur[ir];
        float vp = vprev[ir];
        float al = blockReduceSum256((h == 0) ? wreg * vc : 0.0f, red, tid);
        float wn = wreg - al * vc - beta * vp;
        float bn = sqrtf(blockReduceSum256((h == 0) ? wn * wn : 0.0f, red, tid));
        if (tid == 0) { alph[step] = al; bet[step] = bn; }
        if (h == 0) {
            vprev[ir] = vc;
            vcur[ir]  = wn / (bn + 1e-30f);
        }
        beta = bn;
        __syncthreads();
    }

    // ---- 4 needed eigenvalues via Sturm bisection ----
    if (tid < 4) {
        float a[MLZ], b2[MLZ - 1];
        #pragma unroll
        for (int i = 0; i < MLZ; i++) a[i] = alph[i];
        #pragma unroll
        for (int i = 0; i < MLZ - 1; i++) { float bb = bet[i]; b2[i] = bb * bb; }

        float lo = 3.0e38f, hi = -3.0e38f;
        #pragma unroll
        for (int i = 0; i < MLZ; i++) {
            float rad = 0.0f;
            if (i > 0)       rad += fabsf(bet[i - 1]);
            if (i < MLZ - 1) rad += fabsf(bet[i]);
            lo = fminf(lo, a[i] - rad);
            hi = fmaxf(hi, a[i] + rad);
        }

        int nneg = sturm_count(a, b2, 0.0f);
        int k;
        if      (tid == 0) k = 0;
        else if (tid == 1) k = MLZ - 1;
        else if (tid == 2) { k = nneg - 1; if (k < 0) k = 0; if (k > MLZ - 1) k = MLZ - 1; }
        else               { k = nneg;     if (k > MLZ - 1) k = MLZ - 1; }

        float l = lo, hbd = hi;
        #pragma unroll 1
        for (int it = 0; it < 44; it++) {
            float mid = 0.5f * (l + hbd);
            if (sturm_count(a, b2, mid) > k) hbd = mid; else l = mid;
        }
        sc[tid] = fabsf(0.5f * (l + hbd));
    }
    __syncthreads();
    if (tid == 0) {
        float mx = fmaxf(sc[0], sc[1]);
        float mn = fminf(sc[2], sc[3]);
        g_scr[b]      = mx * mx;
        g_scr[NB + b] = mn * mn;
        __threadfence();
        unsigned t = atomicAdd(&g_ctr, 1u);
        amLast = (t == NB - 1);
    }
    __syncthreads();

    // ---- last CTA reduces all batches (fixed order => deterministic) ----
    if (amLast) {
        __threadfence();
        const volatile float* scr = g_scr;
        float s1 = 0.0f, s2 = 0.0f;
        for (int i = tid; i < NB; i += 256) { s1 += scr[i]; s2 += scr[NB + i]; }
        float S1 = blockReduceSum256(s1, red, tid);
        __syncthreads();
        float S2 = blockReduceSum256(s2, red, tid);
        if (tid == 0) {
            out[0] = (S1 - S2) * (1.0f / (float)NB);
            g_ctr = 0;   // reset for next graph replay
        }
    }
}

extern "C" void kernel_launch(void* const* d_in, const int* in_sizes, int n_in,
                              void* d_out, int out_size) {
    const float* net_out = (const float*)d_in[0];
    const float* U1      = (const float*)d_in[1];
    const float* v       = (const float*)d_in[2];
    (void)in_sizes; (void)n_in; (void)out_size;

    static int attr_set = 0;
    if (!attr_set) {
        cudaFuncSetAttribute(spectrum_kernel,
                             cudaFuncAttributeMaxDynamicSharedMemorySize, SMEM_BYTES);
        attr_set = 1;
    }
    spectrum_kernel<<<NB, 256, SMEM_BYTES>>>(net_out, U1, v, (float*)d_out);
}

// round 7
// speedup vs baseline: 1.2476x; 1.2476x over previous
#include <cuda_runtime.h>
#include <math.h>

#define NB   2048
#define NDIM 128
#define MLZ  10
#define KAPPA 0.276f
#define TRI  8256      // 128*129/2
#define LPAD 8448      // packed tri, rows padded to multiple of 4 floats

// smem: Lp[8448] | vcur[128] | vprev[128] | yv[128] | tv[128] | U1s[128]
#define SMEM_FLOATS (LPAD + 5 * NDIM)
#define SMEM_BYTES  (SMEM_FLOATS * 4)

__device__ float    g_scr[2 * NB];   // [0..NB) max^2, [NB..2NB) min^2
__device__ unsigned g_ctr = 0;

__device__ __forceinline__ float blockReduceSum(float v, float* red, int tid) {
    #pragma unroll
    for (int o = 16; o > 0; o >>= 1)
        v += __shfl_xor_sync(0xffffffffu, v, o);
    __syncthreads();                 // protect red[] from previous use
    if ((tid & 31) == 0) red[tid >> 5] = v;
    __syncthreads();
    return (red[0] + red[1]) + (red[2] + red[3]);
}

__device__ __forceinline__ int sturm_count(const float* a, const float* b2, float x) {
    float q = a[0] - x;
    int c = (q < 0.0f);
    #pragma unroll
    for (int i = 1; i < MLZ; i++) {
        float d = q;
        if (fabsf(d) < 1e-25f) d = (d < 0.0f) ? -1e-25f : 1e-25f;
        q = (a[i] - x) - b2[i - 1] / d;
        c += (q < 0.0f);
    }
    return c;
}

__global__ __launch_bounds__(128)
void spectrum_kernel(const float* __restrict__ net_out,
                     const float* __restrict__ U1,
                     const float* __restrict__ vin,
                     float* __restrict__ out) {
    extern __shared__ float sm[];
    float* Lp    = sm;                 // row i (g=i>>2, rm=i&3) at float4 idx (g+1)*(2g+rm)
    float* vcur  = sm + LPAD;
    float* vprev = vcur + NDIM;
    float* yv    = vprev + NDIM;
    float* tv    = yv + NDIM;
    float* U1s   = tv + NDIM;

    __shared__ float red[4];
    __shared__ float alph[MLZ], bet[MLZ], sc[4];
    __shared__ int   amLast;

    const int tid = threadIdx.x;
    const int b   = blockIdx.x;

    // ---- zero Lp (padding must be 0) ----
    {
        float4 z = make_float4(0.f, 0.f, 0.f, 0.f);
        float4* L4 = (float4*)Lp;
        #pragma unroll 4
        for (int i = tid; i < LPAD / 4; i += 128) L4[i] = z;
    }
    U1s[tid] = U1[(size_t)b * NDIM + tid];
    float v0 = vin[(size_t)b * NDIM + tid];
    __syncthreads();

    // ---- build padded packed Lp from gmem packed tri (coalesced float4 reads) ----
    {
        const float4* src4 = (const float4*)(net_out + (size_t)b * TRI);
        for (int idx = tid; idx < TRI / 4; idx += 128) {
            float4 v4 = src4[idx];
            int k = idx << 2;
            int i = (int)((__fsqrt_rn(8.0f * (float)k + 1.0f) - 1.0f) * 0.5f);
            while ((i + 1) * (i + 2) / 2 <= k) ++i;
            while (i * (i + 1) / 2 > k) --i;
            int j = k - i * (i + 1) / 2;
            float vals[4] = {v4.x, v4.y, v4.z, v4.w};
            #pragma unroll
            for (int m = 0; m < 4; m++) {
                int gi = i >> 2, ri = i & 3;
                Lp[4 * (gi + 1) * (2 * gi + ri) + j] = vals[m];
                if (++j > i) { ++i; j = 0; }
            }
        }
    }

    // vn = v / ||v||  (reduce barriers publish Lp/U1s too)
    float nrm = sqrtf(blockReduceSum(v0 * v0, red, tid));
    vcur[tid]  = v0 / nrm;
    vprev[tid] = 0.0f;

    // ---- dd_opt stencil constants ----
    const int ii = tid >> 4, jj = (tid >> 1) & 7, cc = tid & 1;
    const int xip = (((ii + 1) & 7) << 4) | (jj << 1) | cc;
    const int xim = (((ii - 1) & 7) << 4) | (jj << 1) | cc;
    const int xjp = (ii << 4) | (((jj + 1) & 7) << 1) | cc;
    const int xjm = (ii << 4) | (((jj - 1) & 7) << 1) | cc;
    const float c_u0  = U1s[((ii << 3) + jj) << 1];
    const float c_u1  = U1s[(((ii << 3) + jj) << 1) + 1];
    const float c_u0m = U1s[((((ii - 1) & 7) << 3) + jj) << 1];
    const float c_u1m = U1s[(((ii << 3) + ((jj - 1) & 7)) << 1) + 1];

    // loop-invariant matvec bases
    const int g    = tid >> 2;
    const int rb4  = (g + 1) * (2 * g + (tid & 3));   // row matvec: this thread's row base (f4)
    const int mb0  = (tid & ~31) >> 2;                // col matvec: warp-uniform first i-group
    const float4* Lr4 = (const float4*)Lp;
    const float4* yv4 = (const float4*)yv;
    const float4* tv4 = (const float4*)tv;

    float beta = 0.0f;
    __syncthreads();   // vcur visible

    for (int step = 0; step < MLZ; step++) {
        // ---- y = D x (hop stencil) ----
        {
            float xc  = vcur[tid];
            float hop = c_u0  * vcur[xip] + c_u1  * vcur[xjp]
                      + c_u0m * vcur[xim] + c_u1m * vcur[xjm];
            yv[tid] = xc - KAPPA * hop;
        }
        __syncthreads();

        // ---- t_j = sum_{i>=j} L[i,j] y_i ----
        // warp-synchronized rows i = 4m+k; lane j = tid -> consecutive floats (conflict-free)
        // addr(row 4m+k) = 4(m+1)(2m+k) + tid ; delta over m: 16m+16+4k
        {
            float a0 = 0.f, a1 = 0.f, a2 = 0.f, a3 = 0.f;
            int b0 = (((mb0 + 1) * (2 * mb0    )) << 2) + tid;
            int b1 = (((mb0 + 1) * (2 * mb0 + 1)) << 2) + tid;
            int b2 = (((mb0 + 1) * (2 * mb0 + 2)) << 2) + tid;
            int b3 = (((mb0 + 1) * (2 * mb0 + 3)) << 2) + tid;
            int dinc = (mb0 << 4) + 16;

            // peel: first 8 i-groups contain rows with i < j for some lanes
            #pragma unroll
            for (int p = 0; p < 8; p++) {
                const int m  = mb0 + p;
                const int i0 = m << 2;
                float4 y4 = yv4[m];
                float l0 = Lp[b0], l1 = Lp[b1], l2 = Lp[b2], l3 = Lp[b3];
                if (i0     >= tid) a0 += l0 * y4.x;
                if (i0 + 1 >= tid) a1 += l1 * y4.y;
                if (i0 + 2 >= tid) a2 += l2 * y4.z;
                if (i0 + 3 >= tid) a3 += l3 * y4.w;
                b0 += dinc; b1 += dinc + 4; b2 += dinc + 8; b3 += dinc + 12;
                dinc += 16;
            }
            // clean tail: all rows >= every lane's column (no predicates)
            #pragma unroll 4
            for (int m = mb0 + 8; m < 32; m++) {
                float4 y4 = yv4[m];
                a0 += Lp[b0] * y4.x;
                a1 += Lp[b1] * y4.y;
                a2 += Lp[b2] * y4.z;
                a3 += Lp[b3] * y4.w;
                b0 += dinc; b1 += dinc + 4; b2 += dinc + 8; b3 += dinc + 12;
                dinc += 16;
            }
            tv[tid] = (a0 + a1) + (a2 + a3);
        }
        __syncthreads();

        // ---- w_i = sum_{j<=i} L[i,j] t_j : thread = row, float4 + uniform bcast ----
        float wacc;
        {
            float ax = 0.f, ay = 0.f, az = 0.f, aw = 0.f;
            #pragma unroll 4
            for (int q = 0; q <= g; q++) {
                float4 l  = Lr4[rb4 + q];
                float4 t4 = tv4[q];
                ax += l.x * t4.x; ay += l.y * t4.y;
                az += l.z * t4.z; aw += l.w * t4.w;
            }
            wacc = (ax + ay) + (az + aw);
        }

        // ---- Lanczos recurrence (explicit, matches reference math) ----
        float al = blockReduceSum(wacc * vcur[tid], red, tid);
        float wn = wacc - al * vcur[tid] - beta * vprev[tid];
        float bn = sqrtf(blockReduceSum(wn * wn, red, tid));
        if (tid == 0) { alph[step] = al; bet[step] = bn; }
        vprev[tid] = vcur[tid];
        vcur[tid]  = wn / (bn + 1e-30f);
        beta = bn;
        __syncthreads();
    }

    // ---- 4 needed eigenvalues via Sturm bisection ----
    if (tid < 4) {
        float a[MLZ], b2[MLZ - 1];
        #pragma unroll
        for (int i = 0; i < MLZ; i++) a[i] = alph[i];
        #pragma unroll
        for (int i = 0; i < MLZ - 1; i++) { float bb = bet[i]; b2[i] = bb * bb; }

        float lo = 3.0e38f, hi = -3.0e38f;
        #pragma unroll
        for (int i = 0; i < MLZ; i++) {
            float rad = 0.0f;
            if (i > 0)       rad += fabsf(bet[i - 1]);
            if (i < MLZ - 1) rad += fabsf(bet[i]);
            lo = fminf(lo, a[i] - rad);
            hi = fmaxf(hi, a[i] + rad);
        }

        int nneg = sturm_count(a, b2, 0.0f);
        int k;
        if      (tid == 0) k = 0;
        else if (tid == 1) k = MLZ - 1;
        else if (tid == 2) { k = nneg - 1; if (k < 0) k = 0; if (k > MLZ - 1) k = MLZ - 1; }
        else               { k = nneg;     if (k > MLZ - 1) k = MLZ - 1; }

        float l = lo, h = hi;
        #pragma unroll 1
        for (int it = 0; it < 44; it++) {
            float mid = 0.5f * (l + h);
            if (sturm_count(a, b2, mid) > k) h = mid; else l = mid;
        }
        sc[tid] = fabsf(0.5f * (l + h));
    }
    __syncthreads();
    if (tid == 0) {
        float mx = fmaxf(sc[0], sc[1]);
        float mn = fminf(sc[2], sc[3]);
        g_scr[b]      = mx * mx;
        g_scr[NB + b] = mn * mn;
        __threadfence();
        unsigned t = atomicAdd(&g_ctr, 1u);
        amLast = (t == NB - 1);
    }
    __syncthreads();

    // ---- last CTA reduces all batches (fixed order => deterministic) ----
    if (amLast) {
        __threadfence();
        const volatile float* scr = g_scr;
        float s1 = 0.0f, s2 = 0.0f;
        for (int i = tid; i < NB; i += 128) { s1 += scr[i]; s2 += scr[NB + i]; }
        float S1 = blockReduceSum(s1, red, tid);
        __syncthreads();
        float S2 = blockReduceSum(s2, red, tid);
        if (tid == 0) {
            out[0] = (S1 - S2) * (1.0f / (float)NB);
            g_ctr = 0;   // reset for next graph replay
        }
    }
}

extern "C" void kernel_launch(void* const* d_in, const int* in_sizes, int n_in,
                              void* d_out, int out_size) {
    const float* net_out = (const float*)d_in[0];
    const float* U1      = (const float*)d_in[1];
    const float* v       = (const float*)d_in[2];
    (void)in_sizes; (void)n_in; (void)out_size;

    spectrum_kernel<<<NB, 128, SMEM_BYTES>>>(net_out, U1, v, (float*)d_out);
}

// round 8
// speedup vs baseline: 1.6362x; 1.3114x over previous
#include <cuda_runtime.h>
#include <math.h>

#define NB   2048
#define NDIM 128
#define MLZ  10
#define KAPPA 0.276f
#define TRI  8256      // 128*129/2
#define LPAD 8448      // packed tri, rows padded to multiple of 4 floats

// smem: Lp[8448] | vcur[128] | vprev[128] | yv[128] | tv[128] | U1s[128]
#define SMEM_FLOATS (LPAD + 5 * NDIM)
#define SMEM_BYTES  (SMEM_FLOATS * 4)

__device__ float    g_scr[2 * NB];   // [0..NB) max^2, [NB..2NB) min^2
__device__ unsigned g_ctr = 0;

__device__ __forceinline__ float blockReduceSum(float v, float* red, int tid) {
    #pragma unroll
    for (int o = 16; o > 0; o >>= 1)
        v += __shfl_xor_sync(0xffffffffu, v, o);
    __syncthreads();                 // protect red[] from previous use
    if ((tid & 31) == 0) red[tid >> 5] = v;
    __syncthreads();
    return (red[0] + red[1]) + (red[2] + red[3]);
}

// #eigenvalues of the 10x10 symmetric tridiagonal < x (Sturm / LDL recurrence).
// __fdividef: sign-decision only, bisection is robust to ulp-level division error.
__device__ __forceinline__ int sturm_count(const float* a, const float* b2, float x) {
    float q = a[0] - x;
    int c = (q < 0.0f);
    #pragma unroll
    for (int i = 1; i < MLZ; i++) {
        float d = q;
        if (fabsf(d) < 1e-25f) d = (d < 0.0f) ? -1e-25f : 1e-25f;
        q = (a[i] - x) - __fdividef(b2[i - 1], d);
        c += (q < 0.0f);
    }
    return c;
}

__global__ __launch_bounds__(128)
void spectrum_kernel(const float* __restrict__ net_out,
                     const float* __restrict__ U1,
                     const float* __restrict__ vin,
                     float* __restrict__ out) {
    extern __shared__ float sm[];
    float* Lp    = sm;                 // row i (g=i>>2, rm=i&3) at float4 idx (g+1)*(2g+rm)
    float* vcur  = sm + LPAD;
    float* vprev = vcur + NDIM;
    float* yv    = vprev + NDIM;
    float* tv    = yv + NDIM;
    float* U1s   = tv + NDIM;

    __shared__ float red[4];
    __shared__ float alph[MLZ], bet[MLZ], sc[4];
    __shared__ int   amLast;

    const int tid = threadIdx.x;
    const int b   = blockIdx.x;

    // ---- zero Lp (padding must be 0) ----
    {
        float4 z = make_float4(0.f, 0.f, 0.f, 0.f);
        float4* L4 = (float4*)Lp;
        #pragma unroll 4
        for (int i = tid; i < LPAD / 4; i += 128) L4[i] = z;
    }
    U1s[tid] = U1[(size_t)b * NDIM + tid];
    float v0 = vin[(size_t)b * NDIM + tid];
    __syncthreads();

    // ---- build padded packed Lp from gmem packed tri (coalesced float4 reads) ----
    {
        const float4* src4 = (const float4*)(net_out + (size_t)b * TRI);
        for (int idx = tid; idx < TRI / 4; idx += 128) {
            float4 v4 = src4[idx];
            int k = idx << 2;
            int i = (int)((__fsqrt_rn(8.0f * (float)k + 1.0f) - 1.0f) * 0.5f);
            while ((i + 1) * (i + 2) / 2 <= k) ++i;
            while (i * (i + 1) / 2 > k) --i;
            int j = k - i * (i + 1) / 2;
            float vals[4] = {v4.x, v4.y, v4.z, v4.w};
            #pragma unroll
            for (int m = 0; m < 4; m++) {
                int gi = i >> 2, ri = i & 3;
                Lp[4 * (gi + 1) * (2 * gi + ri) + j] = vals[m];
                if (++j > i) { ++i; j = 0; }
            }
        }
    }

    // vn = v / ||v||  (reduce barriers publish Lp/U1s too)
    float nrm = sqrtf(blockReduceSum(v0 * v0, red, tid));
    vcur[tid]  = v0 / nrm;
    vprev[tid] = 0.0f;

    // ---- dd_opt stencil constants ----
    const int ii = tid >> 4, jj = (tid >> 1) & 7, cc = tid & 1;
    const int xip = (((ii + 1) & 7) << 4) | (jj << 1) | cc;
    const int xim = (((ii - 1) & 7) << 4) | (jj << 1) | cc;
    const int xjp = (ii << 4) | (((jj + 1) & 7) << 1) | cc;
    const int xjm = (ii << 4) | (((jj - 1) & 7) << 1) | cc;
    const float c_u0  = U1s[((ii << 3) + jj) << 1];
    const float c_u1  = U1s[(((ii << 3) + jj) << 1) + 1];
    const float c_u0m = U1s[((((ii - 1) & 7) << 3) + jj) << 1];
    const float c_u1m = U1s[(((ii << 3) + ((jj - 1) & 7)) << 1) + 1];

    // loop-invariant matvec bases
    const int g    = tid >> 2;
    const int rb4  = (g + 1) * (2 * g + (tid & 3));   // row matvec: this thread's row base (f4)
    const int mb0  = (tid & ~31) >> 2;                // col matvec: warp-uniform first i-group
    const int cbase0 = 8 * (mb0 + 1) * mb0 + tid;     // float addr of L[4*mb0][tid]
    const float4* Lr4 = (const float4*)Lp;
    const float4* yv4 = (const float4*)yv;
    const float4* tv4 = (const float4*)tv;

    float beta = 0.0f;
    __syncthreads();   // vcur visible

    for (int step = 0; step < MLZ; step++) {
        // ---- y = D x (hop stencil) ----
        {
            float xc  = vcur[tid];
            float hop = c_u0  * vcur[xip] + c_u1  * vcur[xjp]
                      + c_u0m * vcur[xim] + c_u1m * vcur[xjm];
            yv[tid] = xc - KAPPA * hop;
        }
        __syncthreads();

        // ---- t_j = sum_{i>=j} L[i,j] y_i ----
        // warp-synchronized i; lane j = tid -> 32 consecutive floats per warp (conflict-free)
        {
            float a0 = 0.f, a1 = 0.f, a2 = 0.f, a3 = 0.f;
            int base = cbase0;          // float addr of L[i][j] for current i
            int len  = 4 * (mb0 + 1);   // current row length in floats
            for (int m = mb0; m < 32; m++) {
                float4 y4 = yv4[m];
                int i0 = m << 2;
                float l0 = Lp[base]; base += len;
                float l1 = Lp[base]; base += len;
                float l2 = Lp[base]; base += len;
                float l3 = Lp[base]; base += len;
                if (i0     >= tid) a0 += l0 * y4.x;
                if (i0 + 1 >= tid) a1 += l1 * y4.y;
                if (i0 + 2 >= tid) a2 += l2 * y4.z;
                if (i0 + 3 >= tid) a3 += l3 * y4.w;
                len += 4;
            }
            tv[tid] = (a0 + a1) + (a2 + a3);
        }
        __syncthreads();

        // ---- w_i = sum_{j<=i} L[i,j] t_j : thread = row, float4 + uniform bcast ----
        float wacc;
        {
            float ax = 0.f, ay = 0.f, az = 0.f, aw = 0.f;
            #pragma unroll 4
            for (int q = 0; q <= g; q++) {
                float4 l  = Lr4[rb4 + q];
                float4 t4 = tv4[q];
                ax += l.x * t4.x; ay += l.y * t4.y;
                az += l.z * t4.z; aw += l.w * t4.w;
            }
            wacc = (ax + ay) + (az + aw);
        }

        // ---- Lanczos recurrence (explicit, matches reference math) ----
        float al = blockReduceSum(wacc * vcur[tid], red, tid);
        float wn = wacc - al * vcur[tid] - beta * vprev[tid];
        float bn = sqrtf(blockReduceSum(wn * wn, red, tid));
        if (tid == 0) { alph[step] = al; bet[step] = bn; }
        vprev[tid] = vcur[tid];
        vcur[tid]  = wn / (bn + 1e-30f);
        beta = bn;
        __syncthreads();
    }

    // ---- eigen tail: warp per target, 32-way multisection (8 iters ~ 40 bits) ----
    {
        const int wid  = tid >> 5;
        const int lane = tid & 31;

        float a[MLZ], b2[MLZ - 1];
        #pragma unroll
        for (int i = 0; i < MLZ; i++) a[i] = alph[i];
        #pragma unroll
        for (int i = 0; i < MLZ - 1; i++) { float bb = bet[i]; b2[i] = bb * bb; }

        // Gershgorin bounds (redundant per lane, cheap)
        float lo = 3.0e38f, hi = -3.0e38f;
        #pragma unroll
        for (int i = 0; i < MLZ; i++) {
            float rad = 0.0f;
            if (i > 0)       rad += fabsf(bet[i - 1]);
            if (i < MLZ - 1) rad += fabsf(bet[i]);
            lo = fminf(lo, a[i] - rad);
            hi = fmaxf(hi, a[i] + rad);
        }

        int nneg = sturm_count(a, b2, 0.0f);
        int k;
        if      (wid == 0) k = 0;
        else if (wid == 1) k = MLZ - 1;
        else if (wid == 2) { k = nneg - 1; if (k < 0) k = 0; if (k > MLZ - 1) k = MLZ - 1; }
        else               { k = nneg;     if (k > MLZ - 1) k = MLZ - 1; }

        // Each iter: 32 interior probes x(lane) = lo + (lane+1)*wdt, wdt = span/33.
        // count > k  <=>  lambda_k < x.  First flagged lane brackets lambda_k.
        #pragma unroll 1
        for (int it = 0; it < 8; it++) {
            float wdt = (hi - lo) * (1.0f / 33.0f);
            float x   = lo + wdt * (float)(lane + 1);
            int   c   = sturm_count(a, b2, x);
            unsigned m = __ballot_sync(0xffffffffu, c > k);
            int idx = (m == 0u) ? 32 : (__ffs(m) - 1);
            float nlo = lo + wdt * (float)idx;
            float nhi = (idx == 32) ? hi : lo + wdt * (float)(idx + 1);
            lo = nlo; hi = nhi;
        }
        if (lane == 0) sc[wid] = fabsf(0.5f * (lo + hi));
    }
    __syncthreads();

    if (tid == 0) {
        float mx = fmaxf(sc[0], sc[1]);   // max |lambda|
        float mn = fminf(sc[2], sc[3]);   // min |lambda|
        g_scr[b]      = mx * mx;
        g_scr[NB + b] = mn * mn;
        __threadfence();
        unsigned t = atomicAdd(&g_ctr, 1u);
        amLast = (t == NB - 1);
    }
    __syncthreads();

    // ---- last CTA reduces all batches (fixed order => deterministic) ----
    if (amLast) {
        __threadfence();
        const volatile float* scr = g_scr;
        float s1 = 0.0f, s2 = 0.0f;
        for (int i = tid; i < NB; i += 128) { s1 += scr[i]; s2 += scr[NB + i]; }
        float S1 = blockReduceSum(s1, red, tid);
        __syncthreads();
        float S2 = blockReduceSum(s2, red, tid);
        if (tid == 0) {
            out[0] = (S1 - S2) * (1.0f / (float)NB);
            g_ctr = 0;   // reset for next graph replay
        }
    }
}

extern "C" void kernel_launch(void* const* d_in, const int* in_sizes, int n_in,
                              void* d_out, int out_size) {
    const float* net_out = (const float*)d_in[0];
    const float* U1      = (const float*)d_in[1];
    const float* v       = (const float*)d_in[2];
    (void)in_sizes; (void)n_in; (void)out_size;

    spectrum_kernel<<<NB, 128, SMEM_BYTES>>>(net_out, U1, v, (float*)d_out);
}

// round 9
// speedup vs baseline: 1.6807x; 1.0272x over previous
#include <cuda_runtime.h>
#include <math.h>

#define NB   2048
#define NDIM 128
#define MLZ  10
#define KAPPA 0.276f
#define TRI  8256      // 128*129/2
#define LPAD 8448      // packed tri, rows padded to multiple of 4 floats

// smem: Lp[8448] | vcur[128] | vprev[128] | yv[128] | tv[128] | U1s[128]
#define SMEM_FLOATS (LPAD + 5 * NDIM)
#define SMEM_BYTES  (SMEM_FLOATS * 4)

__device__ float    g_scr[2 * NB];   // [0..NB) max^2, [NB..2NB) min^2
__device__ unsigned g_ctr = 0;

__device__ __forceinline__ float blockReduceSum(float v, float* red, int tid) {
    #pragma unroll
    for (int o = 16; o > 0; o >>= 1)
        v += __shfl_xor_sync(0xffffffffu, v, o);
    __syncthreads();                 // protect red[] from previous use
    if ((tid & 31) == 0) red[tid >> 5] = v;
    __syncthreads();
    return (red[0] + red[1]) + (red[2] + red[3]);
}

// #eigenvalues of the 10x10 symmetric tridiagonal < x (Sturm / LDL recurrence).
// __fdividef: sign-decision only, multisection is robust to ulp-level division error.
__device__ __forceinline__ int sturm_count(const float* a, const float* b2, float x) {
    float q = a[0] - x;
    int c = (q < 0.0f);
    #pragma unroll
    for (int i = 1; i < MLZ; i++) {
        float d = q;
        if (fabsf(d) < 1e-25f) d = (d < 0.0f) ? -1e-25f : 1e-25f;
        q = (a[i] - x) - __fdividef(b2[i - 1], d);
        c += (q < 0.0f);
    }
    return c;
}

__global__ __launch_bounds__(128, 6)
void spectrum_kernel(const float* __restrict__ net_out,
                     const float* __restrict__ U1,
                     const float* __restrict__ vin,
                     float* __restrict__ out) {
    extern __shared__ float sm[];
    float* Lp    = sm;                 // row i (g=i>>2, rm=i&3) at float4 idx (g+1)*(2g+rm)
    float* vcur  = sm + LPAD;
    float* vprev = vcur + NDIM;
    float* yv    = vprev + NDIM;
    float* tv    = yv + NDIM;
    float* U1s   = tv + NDIM;

    __shared__ float red[4];
    __shared__ float alph[MLZ], bet[MLZ], sc[4];
    __shared__ int   amLast;

    const int tid = threadIdx.x;
    const int b   = blockIdx.x;

    // ---- zero Lp (padding must be 0) ----
    {
        float4 z = make_float4(0.f, 0.f, 0.f, 0.f);
        float4* L4 = (float4*)Lp;
        #pragma unroll 4
        for (int i = tid; i < LPAD / 4; i += 128) L4[i] = z;
    }
    U1s[tid] = U1[(size_t)b * NDIM + tid];
    float v0 = vin[(size_t)b * NDIM + tid];
    __syncthreads();

    // ---- build padded packed Lp from gmem packed tri (coalesced float4 reads) ----
    {
        const float4* src4 = (const float4*)(net_out + (size_t)b * TRI);
        for (int idx = tid; idx < TRI / 4; idx += 128) {
            float4 v4 = src4[idx];
            int k = idx << 2;
            int i = (int)((__fsqrt_rn(8.0f * (float)k + 1.0f) - 1.0f) * 0.5f);
            while ((i + 1) * (i + 2) / 2 <= k) ++i;
            while (i * (i + 1) / 2 > k) --i;
            int j = k - i * (i + 1) / 2;
            float vals[4] = {v4.x, v4.y, v4.z, v4.w};
            #pragma unroll
            for (int m = 0; m < 4; m++) {
                int gi = i >> 2, ri = i & 3;
                Lp[4 * (gi + 1) * (2 * gi + ri) + j] = vals[m];
                if (++j > i) { ++i; j = 0; }
            }
        }
    }

    // vn = v / ||v||  (reduce barriers publish Lp/U1s too)
    float nrm = sqrtf(blockReduceSum(v0 * v0, red, tid));
    vcur[tid]  = v0 / nrm;
    vprev[tid] = 0.0f;

    // ---- dd_opt stencil constants ----
    const int ii = tid >> 4, jj = (tid >> 1) & 7, cc = tid & 1;
    const int xip = (((ii + 1) & 7) << 4) | (jj << 1) | cc;
    const int xim = (((ii - 1) & 7) << 4) | (jj << 1) | cc;
    const int xjp = (ii << 4) | (((jj + 1) & 7) << 1) | cc;
    const int xjm = (ii << 4) | (((jj - 1) & 7) << 1) | cc;
    const float c_u0  = U1s[((ii << 3) + jj) << 1];
    const float c_u1  = U1s[(((ii << 3) + jj) << 1) + 1];
    const float c_u0m = U1s[((((ii - 1) & 7) << 3) + jj) << 1];
    const float c_u1m = U1s[(((ii << 3) + ((jj - 1) & 7)) << 1) + 1];

    // loop-invariant matvec bases
    const int g    = tid >> 2;
    const int rb4  = (g + 1) * (2 * g + (tid & 3));   // row matvec: this thread's row base (f4)
    const int mb0  = (tid & ~31) >> 2;                // col matvec: warp-uniform first i-group
    const float4* Lr4 = (const float4*)Lp;
    const float4* yv4 = (const float4*)yv;
    const float4* tv4 = (const float4*)tv;

    float beta = 0.0f;
    __syncthreads();   // vcur visible

    for (int step = 0; step < MLZ; step++) {
        // ---- y = D x (hop stencil) ----
        {
            float xc  = vcur[tid];
            float hop = c_u0  * vcur[xip] + c_u1  * vcur[xjp]
                      + c_u0m * vcur[xim] + c_u1m * vcur[xjm];
            yv[tid] = xc - KAPPA * hop;
        }
        __syncthreads();

        // ---- t_j = sum_{i>=j} L[i,j] y_i ----
        // warp-synchronized rows i = 4m+k; lane j = tid -> consecutive floats (conflict-free).
        // addr(row 4m+k) = 4(m+1)(2m+k) + tid; per-m delta = 16m+16+4k -> 4 independent
        // second-order counters, no serial chain through the loads.
        {
            float a0 = 0.f, a1 = 0.f, a2 = 0.f, a3 = 0.f;
            int b0 = (((mb0 + 1) * (2 * mb0    )) << 2) + tid;
            int b1 = (((mb0 + 1) * (2 * mb0 + 1)) << 2) + tid;
            int b2 = (((mb0 + 1) * (2 * mb0 + 2)) << 2) + tid;
            int b3 = (((mb0 + 1) * (2 * mb0 + 3)) << 2) + tid;
            int dinc = (mb0 << 4) + 16;

            // head: 8 i-groups with i < j for some lanes (predicated, NOT unrolled
            // to keep register pressure down)
            #pragma unroll 1
            for (int m = mb0; m < mb0 + 8; m++) {
                const int i0 = m << 2;
                float4 y4 = yv4[m];
                float l0 = Lp[b0], l1 = Lp[b1], l2 = Lp[b2], l3 = Lp[b3];
                if (i0     >= tid) a0 += l0 * y4.x;
                if (i0 + 1 >= tid) a1 += l1 * y4.y;
                if (i0 + 2 >= tid) a2 += l2 * y4.z;
                if (i0 + 3 >= tid) a3 += l3 * y4.w;
                b0 += dinc; b1 += dinc + 4; b2 += dinc + 8; b3 += dinc + 12;
                dinc += 16;
            }
            // tail: all rows >= every lane's column (no predicates)
            #pragma unroll 4
            for (int m = mb0 + 8; m < 32; m++) {
                float4 y4 = yv4[m];
                a0 += Lp[b0] * y4.x;
                a1 += Lp[b1] * y4.y;
                a2 += Lp[b2] * y4.z;
                a3 += Lp[b3] * y4.w;
                b0 += dinc; b1 += dinc + 4; b2 += dinc + 8; b3 += dinc + 12;
                dinc += 16;
            }
            tv[tid] = (a0 + a1) + (a2 + a3);
        }
        __syncthreads();

        // ---- w_i = sum_{j<=i} L[i,j] t_j : thread = row, float4 + uniform bcast ----
        float wacc;
        {
            float ax = 0.f, ay = 0.f, az = 0.f, aw = 0.f;
            #pragma unroll 4
            for (int q = 0; q <= g; q++) {
                float4 l  = Lr4[rb4 + q];
                float4 t4 = tv4[q];
                ax += l.x * t4.x; ay += l.y * t4.y;
                az += l.z * t4.z; aw += l.w * t4.w;
            }
            wacc = (ax + ay) + (az + aw);
        }

        // ---- Lanczos recurrence (explicit, matches reference math) ----
        float al = blockReduceSum(wacc * vcur[tid], red, tid);
        float wn = wacc - al * vcur[tid] - beta * vprev[tid];
        float bn = sqrtf(blockReduceSum(wn * wn, red, tid));
        if (tid == 0) { alph[step] = al; bet[step] = bn; }
        vprev[tid] = vcur[tid];
        vcur[tid]  = wn / (bn + 1e-30f);
        beta = bn;
        __syncthreads();
    }

    // ---- eigen tail: warp per target, 32-way multisection (8 iters ~ 40 bits) ----
    {
        const int wid  = tid >> 5;
        const int lane = tid & 31;

        float a[MLZ], b2[MLZ - 1];
        #pragma unroll
        for (int i = 0; i < MLZ; i++) a[i] = alph[i];
        #pragma unroll
        for (int i = 0; i < MLZ - 1; i++) { float bb = bet[i]; b2[i] = bb * bb; }

        float lo = 3.0e38f, hi = -3.0e38f;
        #pragma unroll
        for (int i = 0; i < MLZ; i++) {
            float rad = 0.0f;
            if (i > 0)       rad += fabsf(bet[i - 1]);
            if (i < MLZ - 1) rad += fabsf(bet[i]);
            lo = fminf(lo, a[i] - rad);
            hi = fmaxf(hi, a[i] + rad);
        }

        int nneg = sturm_count(a, b2, 0.0f);
        int k;
        if      (wid == 0) k = 0;
        else if (wid == 1) k = MLZ - 1;
        else if (wid == 2) { k = nneg - 1; if (k < 0) k = 0; if (k > MLZ - 1) k = MLZ - 1; }
        else               { k = nneg;     if (k > MLZ - 1) k = MLZ - 1; }

        #pragma unroll 1
        for (int it = 0; it < 8; it++) {
            float wdt = (hi - lo) * (1.0f / 33.0f);
            float x   = lo + wdt * (float)(lane + 1);
            int   c   = sturm_count(a, b2, x);
            unsigned m = __ballot_sync(0xffffffffu, c > k);
            int idx = (m == 0u) ? 32 : (__ffs(m) - 1);
            float nlo = lo + wdt * (float)idx;
            float nhi = (idx == 32) ? hi : lo + wdt * (float)(idx + 1);
            lo = nlo; hi = nhi;
        }
        if (lane == 0) sc[wid] = fabsf(0.5f * (lo + hi));
    }
    __syncthreads();

    if (tid == 0) {
        float mx = fmaxf(sc[0], sc[1]);   // max |lambda|
        float mn = fminf(sc[2], sc[3]);   // min |lambda|
        g_scr[b]      = mx * mx;
        g_scr[NB + b] = mn * mn;
        __threadfence();
        unsigned t = atomicAdd(&g_ctr, 1u);
        amLast = (t == NB - 1);
    }
    __syncthreads();

    // ---- last CTA reduces all batches (fixed order => deterministic) ----
    if (amLast) {
        __threadfence();
        const volatile float* scr = g_scr;
        float s1 = 0.0f, s2 = 0.0f;
        for (int i = tid; i < NB; i += 128) { s1 += scr[i]; s2 += scr[NB + i]; }
        float S1 = blockReduceSum(s1, red, tid);
        __syncthreads();
        float S2 = blockReduceSum(s2, red, tid);
        if (tid == 0) {
            out[0] = (S1 - S2) * (1.0f / (float)NB);
            g_ctr = 0;   // reset for next graph replay
        }
    }
}

extern "C" void kernel_launch(void* const* d_in, const int* in_sizes, int n_in,
                              void* d_out, int out_size) {
    const float* net_out = (const float*)d_in[0];
    const float* U1      = (const float*)d_in[1];
    const float* v       = (const float*)d_in[2];
    (void)in_sizes; (void)n_in; (void)out_size;

    spectrum_kernel<<<NB, 128, SMEM_BYTES>>>(net_out, U1, v, (float*)d_out);
}

// round 10
// speedup vs baseline: 1.7039x; 1.0138x over previous
#include <cuda_runtime.h>
#include <math.h>

#define NB   2048
#define NDIM 128
#define MLZ  10
#define KAPPA 0.276f
#define TRI  8256      // 128*129/2
#define LPAD 8448      // packed tri, rows padded to multiple of 4 floats

// smem: Lp[8448] | vcur[128] | vprev[128] | yv[128] | tv[128] | U1s[128]
#define SMEM_FLOATS (LPAD + 5 * NDIM)
#define SMEM_BYTES  (SMEM_FLOATS * 4)

__device__ float    g_scr[2 * NB];   // [0..NB) max^2, [NB..2NB) min^2
__device__ unsigned g_ctr = 0;

union F2 { float2 f; unsigned long long u; };

// Single-sync block reduce. SAFETY CONTRACT: consecutive uses of the SAME buf
// must be separated by at least one other __syncthreads() between the read
// here and the next write here (verified per call site; redA/redB ping-pong).
__device__ __forceinline__ float blockReduceSum1(float v, float* buf, int tid) {
    #pragma unroll
    for (int o = 16; o > 0; o >>= 1)
        v += __shfl_xor_sync(0xffffffffu, v, o);
    if ((tid & 31) == 0) buf[tid >> 5] = v;
    __syncthreads();
    return (buf[0] + buf[1]) + (buf[2] + buf[3]);
}

// #eigenvalues of the 10x10 symmetric tridiagonal < x (Sturm / LDL recurrence).
// __fdividef: sign-decision only, multisection is robust to ulp-level division error.
__device__ __forceinline__ int sturm_count(const float* a, const float* b2, float x) {
    float q = a[0] - x;
    int c = (q < 0.0f);
    #pragma unroll
    for (int i = 1; i < MLZ; i++) {
        float d = q;
        if (fabsf(d) < 1e-25f) d = (d < 0.0f) ? -1e-25f : 1e-25f;
        q = (a[i] - x) - __fdividef(b2[i - 1], d);
        c += (q < 0.0f);
    }
    return c;
}

__global__ __launch_bounds__(128, 6)
void spectrum_kernel(const float* __restrict__ net_out,
                     const float* __restrict__ U1,
                     const float* __restrict__ vin,
                     float* __restrict__ out) {
    extern __shared__ float sm[];
    float* Lp    = sm;                 // row i (g=i>>2, rm=i&3) at float4 idx (g+1)*(2g+rm)
    float* vcur  = sm + LPAD;
    float* vprev = vcur + NDIM;
    float* yv    = vprev + NDIM;
    float* tv    = yv + NDIM;
    float* U1s   = tv + NDIM;

    __shared__ float redA[4], redB[4];
    __shared__ float alph[MLZ], bet[MLZ], sc[4];
    __shared__ int   amLast;

    const int tid = threadIdx.x;
    const int b   = blockIdx.x;

    // ---- zero ONLY the row pads (3-rm floats at the end of row tid) ----
    {
        const int i = tid, g2 = i >> 2, rm = i & 3;
        float* rowL = Lp + 4 * (g2 + 1) * (2 * g2 + rm);
        #pragma unroll
        for (int p = 0; p < 3; p++)
            if (rm + 1 + p <= 3) rowL[i + 1 + p] = 0.0f;
    }
    U1s[tid] = U1[(size_t)b * NDIM + tid];
    float v0 = vin[(size_t)b * NDIM + tid];
    // no sync needed: pad writes / build writes / U1s are disjoint; the
    // norm-reduce's barrier below publishes everything.

    // ---- build padded packed Lp from gmem packed tri (coalesced float4 reads) ----
    {
        const float4* src4 = (const float4*)(net_out + (size_t)b * TRI);
        for (int idx = tid; idx < TRI / 4; idx += 128) {
            float4 v4 = src4[idx];
            int k = idx << 2;
            int i = (int)((__fsqrt_rn(8.0f * (float)k + 1.0f) - 1.0f) * 0.5f);
            while ((i + 1) * (i + 2) / 2 <= k) ++i;
            while (i * (i + 1) / 2 > k) --i;
            int j = k - i * (i + 1) / 2;
            float vals[4] = {v4.x, v4.y, v4.z, v4.w};
            #pragma unroll
            for (int m = 0; m < 4; m++) {
                int gi = i >> 2, ri = i & 3;
                Lp[4 * (gi + 1) * (2 * gi + ri) + j] = vals[m];
                if (++j > i) { ++i; j = 0; }
            }
        }
    }

    // vn = v / ||v||  (this reduce's barrier publishes Lp/U1s too)
    float nrm = sqrtf(blockReduceSum1(v0 * v0, redA, tid));
    vcur[tid]  = v0 / nrm;
    vprev[tid] = 0.0f;

    // ---- dd_opt stencil constants ----
    const int ii = tid >> 4, jj = (tid >> 1) & 7, cc = tid & 1;
    const int xip = (((ii + 1) & 7) << 4) | (jj << 1) | cc;
    const int xim = (((ii - 1) & 7) << 4) | (jj << 1) | cc;
    const int xjp = (ii << 4) | (((jj + 1) & 7) << 1) | cc;
    const int xjm = (ii << 4) | (((jj - 1) & 7) << 1) | cc;
    const float c_u0  = U1s[((ii << 3) + jj) << 1];
    const float c_u1  = U1s[(((ii << 3) + jj) << 1) + 1];
    const float c_u0m = U1s[((((ii - 1) & 7) << 3) + jj) << 1];
    const float c_u1m = U1s[(((ii << 3) + ((jj - 1) & 7)) << 1) + 1];

    // loop-invariant matvec bases
    const int g    = tid >> 2;
    const int rb4  = (g + 1) * (2 * g + (tid & 3));   // row matvec: this thread's row base (f4)
    const int mb0  = (tid & ~31) >> 2;                // col matvec: warp-uniform first i-group
    const float4* Lr4 = (const float4*)Lp;
    const float4* yv4 = (const float4*)yv;
    const float4* tv4 = (const float4*)tv;

    float beta = 0.0f;
    __syncthreads();   // vcur/vprev visible before hop reads neighbors

    for (int step = 0; step < MLZ; step++) {
        // ---- y = D x (hop stencil) ----
        {
            float xc  = vcur[tid];
            float hop = c_u0  * vcur[xip] + c_u1  * vcur[xjp]
                      + c_u0m * vcur[xim] + c_u1m * vcur[xjm];
            yv[tid] = xc - KAPPA * hop;
        }
        __syncthreads();                                    // S1

        // ---- t_j = sum_{i>=j} L[i,j] y_i ----
        // warp-synchronized rows i = 4m+k; lane j = tid -> consecutive floats (conflict-free).
        // 4 independent second-order address counters, no serial chain through the loads.
        {
            float a0 = 0.f, a1 = 0.f, a2 = 0.f, a3 = 0.f;
            int b0 = (((mb0 + 1) * (2 * mb0    )) << 2) + tid;
            int b1 = (((mb0 + 1) * (2 * mb0 + 1)) << 2) + tid;
            int b2 = (((mb0 + 1) * (2 * mb0 + 2)) << 2) + tid;
            int b3 = (((mb0 + 1) * (2 * mb0 + 3)) << 2) + tid;
            int dinc = (mb0 << 4) + 16;

            // head: 8 i-groups with i < j for some lanes (predicated, not unrolled)
            #pragma unroll 1
            for (int m = mb0; m < mb0 + 8; m++) {
                const int i0 = m << 2;
                float4 y4 = yv4[m];
                float l0 = Lp[b0], l1 = Lp[b1], l2 = Lp[b2], l3 = Lp[b3];
                if (i0     >= tid) a0 += l0 * y4.x;
                if (i0 + 1 >= tid) a1 += l1 * y4.y;
                if (i0 + 2 >= tid) a2 += l2 * y4.z;
                if (i0 + 3 >= tid) a3 += l3 * y4.w;
                b0 += dinc; b1 += dinc + 4; b2 += dinc + 8; b3 += dinc + 12;
                dinc += 16;
            }
            // tail: all rows >= every lane's column (no predicates)
            #pragma unroll 4
            for (int m = mb0 + 8; m < 32; m++) {
                float4 y4 = yv4[m];
                a0 += Lp[b0] * y4.x;
                a1 += Lp[b1] * y4.y;
                a2 += Lp[b2] * y4.z;
                a3 += Lp[b3] * y4.w;
                b0 += dinc; b1 += dinc + 4; b2 += dinc + 8; b3 += dinc + 12;
                dinc += 16;
            }
            tv[tid] = (a0 + a1) + (a2 + a3);
        }
        __syncthreads();                                    // S2

        // ---- w_i = sum_{j<=i} L[i,j] t_j : float4 loads + packed f32x2 FMA ----
        float wacc;
        {
            F2 accA, accB; accA.u = 0ull; accB.u = 0ull;
            #pragma unroll 4
            for (int q = 0; q <= g; q++) {
                float4 l  = Lr4[rb4 + q];
                float4 t4 = tv4[q];
                F2 la, lb, ta, tb;
                la.f = make_float2(l.x,  l.y);  lb.f = make_float2(l.z,  l.w);
                ta.f = make_float2(t4.x, t4.y); tb.f = make_float2(t4.z, t4.w);
                asm("fma.rn.f32x2 %0, %1, %2, %0;" : "+l"(accA.u) : "l"(la.u), "l"(ta.u));
                asm("fma.rn.f32x2 %0, %1, %2, %0;" : "+l"(accB.u) : "l"(lb.u), "l"(tb.u));
            }
            wacc = (accA.f.x + accB.f.x) + (accA.f.y + accB.f.y);
        }

        // ---- Lanczos recurrence (explicit, matches reference math) ----
        float al = blockReduceSum1(wacc * vcur[tid], redA, tid);     // S3
        float wn = wacc - al * vcur[tid] - beta * vprev[tid];
        float bn = sqrtf(blockReduceSum1(wn * wn, redB, tid));       // S4
        if (tid == 0) { alph[step] = al; bet[step] = bn; }
        vprev[tid] = vcur[tid];
        vcur[tid]  = wn / (bn + 1e-30f);
        beta = bn;
        __syncthreads();                                    // S5
    }

    // ---- eigen tail: warp per target, 32-way multisection (8 iters ~ 40 bits) ----
    {
        const int wid  = tid >> 5;
        const int lane = tid & 31;

        float a[MLZ], b2[MLZ - 1];
        #pragma unroll
        for (int i = 0; i < MLZ; i++) a[i] = alph[i];
        #pragma unroll
        for (int i = 0; i < MLZ - 1; i++) { float bb = bet[i]; b2[i] = bb * bb; }

        float lo = 3.0e38f, hi = -3.0e38f;
        #pragma unroll
        for (int i = 0; i < MLZ; i++) {
            float rad = 0.0f;
            if (i > 0)       rad += fabsf(bet[i - 1]);
            if (i < MLZ - 1) rad += fabsf(bet[i]);
            lo = fminf(lo, a[i] - rad);
            hi = fmaxf(hi, a[i] + rad);
        }

        int nneg = sturm_count(a, b2, 0.0f);
        int k;
        if      (wid == 0) k = 0;
        else if (wid == 1) k = MLZ - 1;
        else if (wid == 2) { k = nneg - 1; if (k < 0) k = 0; if (k > MLZ - 1) k = MLZ - 1; }
        else               { k = nneg;     if (k > MLZ - 1) k = MLZ - 1; }

        #pragma unroll 1
        for (int it = 0; it < 8; it++) {
            float wdt = (hi - lo) * (1.0f / 33.0f);
            float x   = lo + wdt * (float)(lane + 1);
            int   c   = sturm_count(a, b2, x);
            unsigned m = __ballot_sync(0xffffffffu, c > k);
            int idx = (m == 0u) ? 32 : (__ffs(m) - 1);
            float nlo = lo + wdt * (float)idx;
            float nhi = (idx == 32) ? hi : lo + wdt * (float)(idx + 1);
            lo = nlo; hi = nhi;
        }
        if (lane == 0) sc[wid] = fabsf(0.5f * (lo + hi));
    }
    __syncthreads();

    if (tid == 0) {
        float mx = fmaxf(sc[0], sc[1]);   // max |lambda|
        float mn = fminf(sc[2], sc[3]);   // min |lambda|
        g_scr[b]      = mx * mx;
        g_scr[NB + b] = mn * mn;
        __threadfence();
        unsigned t = atomicAdd(&g_ctr, 1u);
        amLast = (t == NB - 1);
    }
    __syncthreads();

    // ---- last CTA reduces all batches (fixed order => deterministic) ----
    if (amLast) {
        __threadfence();
        const volatile float* scr = g_scr;
        float s1 = 0.0f, s2 = 0.0f;
        for (int i = tid; i < NB; i += 128) { s1 += scr[i]; s2 += scr[NB + i]; }
        float S1 = blockReduceSum1(s1, redA, tid);
        float S2 = blockReduceSum1(s2, redB, tid);
        if (tid == 0) {
            out[0] = (S1 - S2) * (1.0f / (float)NB);
            g_ctr = 0;   // reset for next graph replay
        }
    }
}

extern "C" void kernel_launch(void* const* d_in, const int* in_sizes, int n_in,
                              void* d_out, int out_size) {
    const float* net_out = (const float*)d_in[0];
    const float* U1      = (const float*)d_in[1];
    const float* v       = (const float*)d_in[2];
    (void)in_sizes; (void)n_in; (void)out_size;

    spectrum_kernel<<<NB, 128, SMEM_BYTES>>>(net_out, U1, v, (float*)d_out);
}